// round 16
// baseline (speedup 1.0000x reference)
#include <cuda_runtime.h>
#include <stdint.h>
#include <math.h>

#define NB 2
#define NS 2048
#define ND 1024
#define NH 16
#define NDK 64
#define MTOT (NB * NS)   // 4096 rows of X

// Scratch: transposed inputs Xt[z][d][b*s] (48 MB), projected Q/K/V [B,S,D],
// full score matrix in order-preserving mono-u32 [BH][S][S] (512 MB).
__device__ float g_Xt[3][(size_t)ND * MTOT];
__device__ float g_Qp[NB * NS * ND];
__device__ float g_Kp[NB * NS * ND];
__device__ float g_Vp[NB * NS * ND];
__device__ unsigned g_S[(size_t)NB * NH * NS * NS];

// ---------------------------------------------------------------------------
// Helpers
// ---------------------------------------------------------------------------
__device__ __forceinline__ float warp_max(float v) {
#pragma unroll
    for (int off = 16; off > 0; off >>= 1)
        v = fmaxf(v, __shfl_xor_sync(0xffffffffu, v, off));
    return v;
}
__device__ __forceinline__ float warp_sum(float v) {
#pragma unroll
    for (int off = 16; off > 0; off >>= 1)
        v += __shfl_xor_sync(0xffffffffu, v, off);
    return v;
}
// Monotone float<->uint transform: u-order == float-order (finite values).
__device__ __forceinline__ unsigned f2mono(float f) {
    unsigned b = __float_as_uint(f);
    return (b & 0x80000000u) ? ~b : (b | 0x80000000u);
}
__device__ __forceinline__ float mono2f(unsigned u) {
    unsigned b = (u & 0x80000000u) ? (u ^ 0x80000000u) : ~u;
    return __uint_as_float(b);
}
// Packed dual-FMA: acc.{lo,hi} += a.{lo,hi} * b.{lo,hi}
__device__ __forceinline__ void ffma2(unsigned long long& acc,
                                      unsigned long long a,
                                      unsigned long long b) {
    asm("fma.rn.f32x2 %0, %1, %2, %0;" : "+l"(acc) : "l"(a), "l"(b));
}
// Duplicate a float into both halves of a packed f32x2
__device__ __forceinline__ unsigned long long dup2(float x) {
    unsigned long long r;
    asm("mov.b64 %0, {%1, %1};" : "=l"(r) : "f"(x));
    return r;
}
union F4U2 { float4 f; unsigned long long u[2]; float s[4]; };

__device__ __forceinline__ void cp_async16(unsigned saddr, const void* gaddr) {
    asm volatile("cp.async.cg.shared.global [%0], [%1], 16;\n"
                 :: "r"(saddr), "l"(gaddr));
}
__device__ __forceinline__ void cp_commit() {
    asm volatile("cp.async.commit_group;\n" ::: "memory");
}
__device__ __forceinline__ void cp_wait_all() {
    asm volatile("cp.async.wait_group 0;\n" ::: "memory");
}

// ---------------------------------------------------------------------------
// Transpose X[z]: [M=4096][D=1024] -> Xt[z]: [D][M]. Exact copy (bitwise).
// 32x32 tiles, 32x8 threads, smem 32x33. Grid (128, 32, 3).
// ---------------------------------------------------------------------------
__global__ __launch_bounds__(256) void transpose_kernel(
    const float* __restrict__ X0, const float* __restrict__ X1,
    const float* __restrict__ X2)
{
    __shared__ float tile[32][33];
    const int z = blockIdx.z;
    const float* X = (z == 0) ? X0 : (z == 1) ? X1 : X2;
    float* Xt = g_Xt[z];

    const int m0 = blockIdx.x * 32;   // row range in X (M)
    const int d0 = blockIdx.y * 32;   // col range in X (D)
    const int tx = threadIdx.x & 31;
    const int ty = threadIdx.x >> 5;  // 0..7

#pragma unroll
    for (int j = 0; j < 4; j++) {
        const int r = ty + j * 8;
        tile[r][tx] = X[(size_t)(m0 + r) * ND + d0 + tx];
    }
    __syncthreads();
#pragma unroll
    for (int j = 0; j < 4; j++) {
        const int r = ty + j * 8;
        Xt[(size_t)(d0 + r) * MTOT + m0 + tx] = tile[tx][r];
    }
}

// ---------------------------------------------------------------------------
// Projection GEMM (FFMA2, async-staged): C = relu(Xt^T @ W + bias).
// Both operands k-major in global (Xt pre-transposed) -> cp.async staging,
// BK=32, double-buffered, ONE barrier per 32-k step (32 total).
// Inner microtile identical to R7 -> bit-identical output.
// Grid (8, 32, 3), 256 threads, dynamic smem 64 KB, 2 CTAs/SM.
// ---------------------------------------------------------------------------
#define PROJ_SMEM (2 * 32 * 128 * 2 * 4)   // 2 buf x 32 k x 128 x {A,W} x fp32

__global__ __launch_bounds__(256, 2) void proj_kernel(
    const float* __restrict__ W0, const float* __restrict__ B0,
    const float* __restrict__ W1, const float* __restrict__ B1,
    const float* __restrict__ W2, const float* __restrict__ B2)
{
    extern __shared__ float psm[];
    // layout: As[buf][k][m] at psm + buf*8192, Ws[buf][k][n] at +4096 per buf
    const int N = ND, K = ND;
    const int z = blockIdx.z;
    const float* W    = (z == 0) ? W0 : (z == 1) ? W1 : W2;
    const float* bias = (z == 0) ? B0 : (z == 1) ? B1 : B2;
    const float* Xt   = g_Xt[z];
    float* C          = (z == 0) ? g_Qp : (z == 1) ? g_Kp : g_Vp;

    const int tid = threadIdx.x;
    const int tx = tid & 15;
    const int ty = tid >> 4;
    const int brow = blockIdx.y * 128;
    const int bcol = blockIdx.x * 128;

    const unsigned sbase = (unsigned)__cvta_generic_to_shared(psm);

    // cp.async mapping: 1024 float4 per operand slab / 256 threads = 4 each
    // slot s: kk = s>>5 (k row), cc = (s&31)*4 (col)
    unsigned long long accp[8][4];
#pragma unroll
    for (int i = 0; i < 8; i++)
#pragma unroll
        for (int q = 0; q < 4; q++) accp[i][q] = 0ull;

    // issue step 0
    {
#pragma unroll
        for (int j = 0; j < 4; j++) {
            const int s = tid + j * 256;
            const int kk = s >> 5, cc = (s & 31) << 2;
            cp_async16(sbase + (unsigned)((kk * 128 + cc) * 4),
                       Xt + (size_t)kk * MTOT + brow + cc);
            cp_async16(sbase + (unsigned)((4096 + kk * 128 + cc) * 4),
                       W + (size_t)kk * N + bcol + cc);
        }
        cp_commit();
    }

    for (int step = 0; step < 32; step++) {
        cp_wait_all();
        __syncthreads();

        const int p = step & 1;
        // issue step+1 into the other buffer (last read in step-1; all
        // threads are past that step's barrier)
        if (step < 31) {
            const int k0n = (step + 1) * 32;
            const unsigned ob = (unsigned)(((step + 1) & 1) * 8192 * 4);
#pragma unroll
            for (int j = 0; j < 4; j++) {
                const int s = tid + j * 256;
                const int kk = s >> 5, cc = (s & 31) << 2;
                cp_async16(sbase + ob + (unsigned)((kk * 128 + cc) * 4),
                           Xt + (size_t)(k0n + kk) * MTOT + brow + cc);
                cp_async16(sbase + ob + (unsigned)((4096 + kk * 128 + cc) * 4),
                           W + (size_t)(k0n + kk) * N + bcol + cc);
            }
            cp_commit();
        }

        const float* As = psm + p * 8192;
        const float* Ws = As + 4096;
#pragma unroll
        for (int k = 0; k < 32; k++) {
            float4 av0 = *(const float4*)&As[k * 128 + ty * 4];
            float4 av1 = *(const float4*)&As[k * 128 + 64 + ty * 4];
            F4U2 b0, b1;
            b0.f = *(const float4*)&Ws[k * 128 + tx * 4];
            b1.f = *(const float4*)&Ws[k * 128 + 64 + tx * 4];
            unsigned long long bp[4] = {b0.u[0], b0.u[1], b1.u[0], b1.u[1]};
            float arr[8] = {av0.x, av0.y, av0.z, av0.w, av1.x, av1.y, av1.z, av1.w};
#pragma unroll
            for (int i = 0; i < 8; i++) {
                unsigned long long ad = dup2(arr[i]);
#pragma unroll
                for (int q = 0; q < 4; q++) ffma2(accp[i][q], ad, bp[q]);
            }
        }
        __syncthreads();
    }

#pragma unroll
    for (int i = 0; i < 8; i++) {
        const int r = brow + ((i < 4) ? (ty * 4 + i) : (64 + ty * 4 + (i - 4)));
        const float2* ap = (const float2*)&accp[i][0];
        {
            const int c = bcol + tx * 4;
            float4 v;
            v.x = fmaxf(ap[0].x + bias[c + 0], 0.0f);
            v.y = fmaxf(ap[0].y + bias[c + 1], 0.0f);
            v.z = fmaxf(ap[1].x + bias[c + 2], 0.0f);
            v.w = fmaxf(ap[1].y + bias[c + 3], 0.0f);
            *(float4*)(C + (size_t)r * N + c) = v;
        }
        {
            const int c = bcol + 64 + tx * 4;
            float4 v;
            v.x = fmaxf(ap[2].x + bias[c + 0], 0.0f);
            v.y = fmaxf(ap[2].y + bias[c + 1], 0.0f);
            v.z = fmaxf(ap[3].x + bias[c + 2], 0.0f);
            v.w = fmaxf(ap[3].y + bias[c + 3], 0.0f);
            *(float4*)(C + (size_t)r * N + c) = v;
        }
    }
}

// ---------------------------------------------------------------------------
// Phase A: score GEMM (R13 version, verbatim). Per (b,h):
// S = (Qh @ Kh^T) / 8, written as mono-u32. Grid = (16, 16, 32).
// ---------------------------------------------------------------------------
#define SPAD 132
__global__ __launch_bounds__(256, 2) void score_kernel()
{
    __shared__ float As[32][SPAD];   // As[k][m]
    __shared__ float Bs[32][SPAD];   // Bs[k][n]

    const int bh = blockIdx.z;
    const int b = bh >> 4, h = bh & 15;
    const int brow = blockIdx.y * 128;
    const int bcol = blockIdx.x * 128;
    const int tid = threadIdx.x;
    const int tx = tid & 15;
    const int ty = tid >> 4;

    const float* Qb = g_Qp + (size_t)b * NS * ND + h * NDK;
    const float* Kb = g_Kp + (size_t)b * NS * ND + h * NDK;

    unsigned long long accp[8][4];
#pragma unroll
    for (int i = 0; i < 8; i++)
#pragma unroll
        for (int q = 0; q < 4; q++) accp[i][q] = 0ull;

    const int d4 = tid & 7;      // float4 index within 32-wide k chunk
    const int rr = tid >> 3;     // 0..31

    for (int kc = 0; kc < 2; kc++) {
        __syncthreads();
#pragma unroll
        for (int c = 0; c < 4; c++) {
            const int r = rr + c * 32;
            float4 qa = *(const float4*)(Qb + (size_t)(brow + r) * ND + kc * 32 + d4 * 4);
            As[d4 * 4 + 0][r] = qa.x;
            As[d4 * 4 + 1][r] = qa.y;
            As[d4 * 4 + 2][r] = qa.z;
            As[d4 * 4 + 3][r] = qa.w;
            float4 kb = *(const float4*)(Kb + (size_t)(bcol + r) * ND + kc * 32 + d4 * 4);
            Bs[d4 * 4 + 0][r] = kb.x;
            Bs[d4 * 4 + 1][r] = kb.y;
            Bs[d4 * 4 + 2][r] = kb.z;
            Bs[d4 * 4 + 3][r] = kb.w;
        }
        __syncthreads();
#pragma unroll 8
        for (int k = 0; k < 32; k++) {
            float4 av0 = *(const float4*)&As[k][ty * 4];
            float4 av1 = *(const float4*)&As[k][64 + ty * 4];
            F4U2 b0, b1;
            b0.f = *(const float4*)&Bs[k][tx * 4];
            b1.f = *(const float4*)&Bs[k][64 + tx * 4];
            unsigned long long bp[4] = {b0.u[0], b0.u[1], b1.u[0], b1.u[1]};
            float arr[8] = {av0.x, av0.y, av0.z, av0.w, av1.x, av1.y, av1.z, av1.w};
#pragma unroll
            for (int i = 0; i < 8; i++) {
                unsigned long long ad = dup2(arr[i]);
#pragma unroll
                for (int q = 0; q < 4; q++) ffma2(accp[i][q], ad, bp[q]);
            }
        }
    }

    // epilogue: scale by 1/8, mono-transform, store u32
    unsigned* Sb = g_S + (size_t)bh * NS * NS;
#pragma unroll
    for (int i = 0; i < 8; i++) {
        const int row = brow + ((i < 4) ? (ty * 4 + i) : (64 + ty * 4 + (i - 4)));
        unsigned* srow = Sb + (size_t)row * NS;
        const float2* ap = (const float2*)&accp[i][0];
        uint4 u0, u1;
        u0.x = f2mono(ap[0].x * 0.125f);
        u0.y = f2mono(ap[0].y * 0.125f);
        u0.z = f2mono(ap[1].x * 0.125f);
        u0.w = f2mono(ap[1].y * 0.125f);
        u1.x = f2mono(ap[2].x * 0.125f);
        u1.y = f2mono(ap[2].y * 0.125f);
        u1.z = f2mono(ap[3].x * 0.125f);
        u1.w = f2mono(ap[3].y * 0.125f);
        *(uint4*)(srow + bcol + tx * 4) = u0;
        *(uint4*)(srow + bcol + 64 + tx * 4) = u1;
    }
}

// ---------------------------------------------------------------------------
// Phase B: per (b,h,s) row — exact top-32 over the stored mono-u32 scores,
// softmax over survivors, V gather, output. One warp per row; 8-deep
// prefetch ring. (R13 version, verbatim)
// ---------------------------------------------------------------------------
__global__ __launch_bounds__(256) void select_kernel(float* __restrict__ out)
{
    __shared__ float swt[8][32];
    __shared__ int   svi[8][32];

    const int warp = threadIdx.x >> 5;
    const int lane = threadIdx.x & 31;
    const int job = blockIdx.x * 8 + warp;   // 0..65535
    const int bh = job >> 11;
    const int s  = job & 2047;
    const int b = bh >> 4, h = bh & 15;

    const unsigned* srow = g_S + (size_t)bh * NS * NS + (size_t)s * NS;

    // init list from first 32 candidates
    unsigned lu = srow[lane];
    int lidx = lane;
    unsigned umin = __reduce_min_sync(0xffffffffu, lu);
    int minlane = __ffs(__ballot_sync(0xffffffffu, lu == umin)) - 1;

    // 8-deep prefetch ring
    unsigned nxt[8];
#pragma unroll
    for (int j = 0; j < 8; j++) nxt[j] = srow[(1 + j) * 32 + lane];

#pragma unroll 8
    for (int t = 1; t < 64; t++) {
        const unsigned u = nxt[(t - 1) & 7];
        if (t + 8 < 64) nxt[(t - 1) & 7] = srow[(t + 8) * 32 + lane];
        const int base = t * 32;

        unsigned bal = __ballot_sync(0xffffffffu, u > umin);
        while (bal) {
            const int src = __ffs(bal) - 1;
            bal &= bal - 1;
            const unsigned uv = __shfl_sync(0xffffffffu, u, src);
            if (uv > umin) {             // umin warp-uniform -> uniform branch
                if (lane == minlane) { lu = uv; lidx = base + src; }
                umin = __reduce_min_sync(0xffffffffu, lu);
                minlane = __ffs(__ballot_sync(0xffffffffu, lu == umin)) - 1;
            }
        }
    }

    // softmax over the 32 survivors (== reference masked softmax: masked
    // entries contribute exp(-1e9 - max) == 0 in fp32)
    const float lval = mono2f(lu);
    const float m = warp_max(lval);
    const float e = __expf(lval - m);
    const float w = e / warp_sum(e);

    // publish (weight, index) via smem; gather loop uses LDS broadcasts
    swt[warp][lane] = w;
    svi[warp][lane] = lidx;
    __syncwarp();

    // AV gather: lane owns output dims (2*lane, 2*lane+1)
    const float* Vb = g_Vp + (size_t)b * NS * ND + h * NDK + lane * 2;
    float2 acc = make_float2(0.f, 0.f);
#pragma unroll
    for (int t = 0; t < 32; t++) {
        const int   vi = svi[warp][t];
        const float wt = swt[warp][t];
        const float2 v = *(const float2*)(Vb + (size_t)vi * ND);
        acc.x += wt * v.x;
        acc.y += wt * v.y;
    }

    *(float2*)(out + (size_t)(b * NS + s) * ND + h * NDK + lane * 2) = acc;
}

// ---------------------------------------------------------------------------
extern "C" void kernel_launch(void* const* d_in, const int* in_sizes, int n_in,
                              void* d_out, int out_size)
{
    const float* query = (const float*)d_in[0];
    const float* key   = (const float*)d_in[1];
    const float* value = (const float*)d_in[2];
    const float* Wq    = (const float*)d_in[3];
    const float* bq    = (const float*)d_in[4];
    const float* Wk    = (const float*)d_in[5];
    const float* bk    = (const float*)d_in[6];
    const float* Wv    = (const float*)d_in[7];
    const float* bv    = (const float*)d_in[8];
    float* out = (float*)d_out;

    cudaFuncSetAttribute(proj_kernel,
                         cudaFuncAttributeMaxDynamicSharedMemorySize, PROJ_SMEM);

    dim3 tgrid(MTOT / 32, ND / 32, 3);
    transpose_kernel<<<tgrid, 256>>>(query, key, value);

    dim3 pgrid(ND / 128, MTOT / 128, 3);
    proj_kernel<<<pgrid, 256, PROJ_SMEM>>>(Wq, bq, Wk, bk, Wv, bv);

    dim3 sgrid(NS / 128, NS / 128, NB * NH);
    score_kernel<<<sgrid, 256>>>();

    select_kernel<<<(NB * NH * NS) / 8, 256>>>(out);
}

// round 17
// speedup vs baseline: 1.6680x; 1.6680x over previous
#include <cuda_runtime.h>
#include <stdint.h>
#include <math.h>

#define NB 2
#define NS 2048
#define ND 1024
#define NH 16
#define NDK 64

// Scratch: projected Q/K/V [B,S,D] fp32 (head h = cols h*64..h*64+63),
// plus full score matrix in order-preserving mono-u32 [BH][S][S] (512 MB).
__device__ float g_Qp[NB * NS * ND];
__device__ float g_Kp[NB * NS * ND];
__device__ float g_Vp[NB * NS * ND];
__device__ unsigned g_S[(size_t)NB * NH * NS * NS];

// ---------------------------------------------------------------------------
// Helpers
// ---------------------------------------------------------------------------
__device__ __forceinline__ float warp_max(float v) {
#pragma unroll
    for (int off = 16; off > 0; off >>= 1)
        v = fmaxf(v, __shfl_xor_sync(0xffffffffu, v, off));
    return v;
}
__device__ __forceinline__ float warp_sum(float v) {
#pragma unroll
    for (int off = 16; off > 0; off >>= 1)
        v += __shfl_xor_sync(0xffffffffu, v, off);
    return v;
}
// Monotone float<->uint transform: u-order == float-order (finite values).
__device__ __forceinline__ unsigned f2mono(float f) {
    unsigned b = __float_as_uint(f);
    return (b & 0x80000000u) ? ~b : (b | 0x80000000u);
}
__device__ __forceinline__ float mono2f(unsigned u) {
    unsigned b = (u & 0x80000000u) ? (u ^ 0x80000000u) : ~u;
    return __uint_as_float(b);
}
// Packed dual-FMA: acc.{lo,hi} += a.{lo,hi} * b.{lo,hi}
__device__ __forceinline__ void ffma2(unsigned long long& acc,
                                      unsigned long long a,
                                      unsigned long long b) {
    asm("fma.rn.f32x2 %0, %1, %2, %0;" : "+l"(acc) : "l"(a), "l"(b));
}
// Duplicate a float into both halves of a packed f32x2
__device__ __forceinline__ unsigned long long dup2(float x) {
    unsigned long long r;
    asm("mov.b64 %0, {%1, %1};" : "=l"(r) : "f"(x));
    return r;
}
union F4U2 { float4 f; unsigned long long u[2]; float s[4]; };

// ---------------------------------------------------------------------------
// Projection GEMM (FFMA2): C = relu(A @ W + bias), M=4096, N=K=1024, x3.
// (R7/R13 version, local optimum — verbatim)
// ---------------------------------------------------------------------------
__global__ __launch_bounds__(256, 2) void proj_kernel(
    const float* __restrict__ X0, const float* __restrict__ W0, const float* __restrict__ B0,
    const float* __restrict__ X1, const float* __restrict__ W1, const float* __restrict__ B1,
    const float* __restrict__ X2, const float* __restrict__ W2, const float* __restrict__ B2)
{
    const int N = ND, K = ND;
    const int z = blockIdx.z;
    const float* A    = (z == 0) ? X0 : (z == 1) ? X1 : X2;
    const float* W    = (z == 0) ? W0 : (z == 1) ? W1 : W2;
    const float* bias = (z == 0) ? B0 : (z == 1) ? B1 : B2;
    float* C          = (z == 0) ? g_Qp : (z == 1) ? g_Kp : g_Vp;

    __shared__ float As[2][16][128];
    __shared__ float Bs[2][16][128];

    const int tid = threadIdx.x;
    const int tx = tid & 15;
    const int ty = tid >> 4;
    const int brow = blockIdx.y * 128;
    const int bcol = blockIdx.x * 128;

    const int ar = tid >> 1;
    const int ak = (tid & 1) << 3;
    const int wr = tid >> 4;
    const int wc = (tid & 15) << 3;

    unsigned long long accp[8][4];
#pragma unroll
    for (int i = 0; i < 8; i++)
#pragma unroll
        for (int q = 0; q < 4; q++) accp[i][q] = 0ull;

    const float* Aptr = A + (size_t)(brow + ar) * K + ak;
    const float* Wptr = W + (size_t)wr * N + bcol + wc;

    float4 a0 = *(const float4*)(Aptr);
    float4 a1 = *(const float4*)(Aptr + 4);
    float4 w0 = *(const float4*)(Wptr);
    float4 w1 = *(const float4*)(Wptr + 4);

    int p = 0;
    for (int k0 = 0; k0 < K; k0 += 16) {
        As[p][ak + 0][ar] = a0.x;
        As[p][ak + 1][ar] = a0.y;
        As[p][ak + 2][ar] = a0.z;
        As[p][ak + 3][ar] = a0.w;
        As[p][ak + 4][ar] = a1.x;
        As[p][ak + 5][ar] = a1.y;
        As[p][ak + 6][ar] = a1.z;
        As[p][ak + 7][ar] = a1.w;
        *(float4*)&Bs[p][wr][wc] = w0;
        *(float4*)&Bs[p][wr][wc + 4] = w1;
        __syncthreads();
        if (k0 + 16 < K) {
            a0 = *(const float4*)(Aptr + k0 + 16);
            a1 = *(const float4*)(Aptr + k0 + 20);
            w0 = *(const float4*)(Wptr + (size_t)(k0 + 16) * N);
            w1 = *(const float4*)(Wptr + (size_t)(k0 + 16) * N + 4);
        }
#pragma unroll
        for (int k = 0; k < 16; k++) {
            float4 av0 = *(const float4*)&As[p][k][ty * 4];
            float4 av1 = *(const float4*)&As[p][k][64 + ty * 4];
            F4U2 b0, b1;
            b0.f = *(const float4*)&Bs[p][k][tx * 4];
            b1.f = *(const float4*)&Bs[p][k][64 + tx * 4];
            unsigned long long bp[4] = {b0.u[0], b0.u[1], b1.u[0], b1.u[1]};
            float arr[8] = {av0.x, av0.y, av0.z, av0.w, av1.x, av1.y, av1.z, av1.w};
#pragma unroll
            for (int i = 0; i < 8; i++) {
                unsigned long long ad = dup2(arr[i]);
#pragma unroll
                for (int q = 0; q < 4; q++) ffma2(accp[i][q], ad, bp[q]);
            }
        }
        p ^= 1;
    }

#pragma unroll
    for (int i = 0; i < 8; i++) {
        const int r = brow + ((i < 4) ? (ty * 4 + i) : (64 + ty * 4 + (i - 4)));
        const float2* ap = (const float2*)&accp[i][0];
        {
            const int c = bcol + tx * 4;
            float4 v;
            v.x = fmaxf(ap[0].x + bias[c + 0], 0.0f);
            v.y = fmaxf(ap[0].y + bias[c + 1], 0.0f);
            v.z = fmaxf(ap[1].x + bias[c + 2], 0.0f);
            v.w = fmaxf(ap[1].y + bias[c + 3], 0.0f);
            *(float4*)(C + (size_t)r * N + c) = v;
        }
        {
            const int c = bcol + 64 + tx * 4;
            float4 v;
            v.x = fmaxf(ap[2].x + bias[c + 0], 0.0f);
            v.y = fmaxf(ap[2].y + bias[c + 1], 0.0f);
            v.z = fmaxf(ap[3].x + bias[c + 2], 0.0f);
            v.w = fmaxf(ap[3].y + bias[c + 3], 0.0f);
            *(float4*)(C + (size_t)r * N + c) = v;
        }
    }
}

// ---------------------------------------------------------------------------
// Phase A: score GEMM (R13 version, verbatim). Per (b,h):
// S = (Qh @ Kh^T) / 8, written as mono-u32. Grid = (16, 16, 32).
// ---------------------------------------------------------------------------
#define SPAD 132
__global__ __launch_bounds__(256, 2) void score_kernel()
{
    __shared__ float As[32][SPAD];   // As[k][m]
    __shared__ float Bs[32][SPAD];   // Bs[k][n]

    const int bh = blockIdx.z;
    const int b = bh >> 4, h = bh & 15;
    const int brow = blockIdx.y * 128;
    const int bcol = blockIdx.x * 128;
    const int tid = threadIdx.x;
    const int tx = tid & 15;
    const int ty = tid >> 4;

    const float* Qb = g_Qp + (size_t)b * NS * ND + h * NDK;
    const float* Kb = g_Kp + (size_t)b * NS * ND + h * NDK;

    unsigned long long accp[8][4];
#pragma unroll
    for (int i = 0; i < 8; i++)
#pragma unroll
        for (int q = 0; q < 4; q++) accp[i][q] = 0ull;

    const int d4 = tid & 7;      // float4 index within 32-wide k chunk
    const int rr = tid >> 3;     // 0..31

    for (int kc = 0; kc < 2; kc++) {
        __syncthreads();
#pragma unroll
        for (int c = 0; c < 4; c++) {
            const int r = rr + c * 32;
            float4 qa = *(const float4*)(Qb + (size_t)(brow + r) * ND + kc * 32 + d4 * 4);
            As[d4 * 4 + 0][r] = qa.x;
            As[d4 * 4 + 1][r] = qa.y;
            As[d4 * 4 + 2][r] = qa.z;
            As[d4 * 4 + 3][r] = qa.w;
            float4 kb = *(const float4*)(Kb + (size_t)(bcol + r) * ND + kc * 32 + d4 * 4);
            Bs[d4 * 4 + 0][r] = kb.x;
            Bs[d4 * 4 + 1][r] = kb.y;
            Bs[d4 * 4 + 2][r] = kb.z;
            Bs[d4 * 4 + 3][r] = kb.w;
        }
        __syncthreads();
#pragma unroll 8
        for (int k = 0; k < 32; k++) {
            float4 av0 = *(const float4*)&As[k][ty * 4];
            float4 av1 = *(const float4*)&As[k][64 + ty * 4];
            F4U2 b0, b1;
            b0.f = *(const float4*)&Bs[k][tx * 4];
            b1.f = *(const float4*)&Bs[k][64 + tx * 4];
            unsigned long long bp[4] = {b0.u[0], b0.u[1], b1.u[0], b1.u[1]};
            float arr[8] = {av0.x, av0.y, av0.z, av0.w, av1.x, av1.y, av1.z, av1.w};
#pragma unroll
            for (int i = 0; i < 8; i++) {
                unsigned long long ad = dup2(arr[i]);
#pragma unroll
                for (int q = 0; q < 4; q++) ffma2(accp[i][q], ad, bp[q]);
            }
        }
    }

    // epilogue: scale by 1/8, mono-transform, store u32
    unsigned* Sb = g_S + (size_t)bh * NS * NS;
#pragma unroll
    for (int i = 0; i < 8; i++) {
        const int row = brow + ((i < 4) ? (ty * 4 + i) : (64 + ty * 4 + (i - 4)));
        unsigned* srow = Sb + (size_t)row * NS;
        const float2* ap = (const float2*)&accp[i][0];
        uint4 u0, u1;
        u0.x = f2mono(ap[0].x * 0.125f);
        u0.y = f2mono(ap[0].y * 0.125f);
        u0.z = f2mono(ap[1].x * 0.125f);
        u0.w = f2mono(ap[1].y * 0.125f);
        u1.x = f2mono(ap[2].x * 0.125f);
        u1.y = f2mono(ap[2].y * 0.125f);
        u1.z = f2mono(ap[3].x * 0.125f);
        u1.w = f2mono(ap[3].y * 0.125f);
        *(uint4*)(srow + bcol + tx * 4) = u0;
        *(uint4*)(srow + bcol + 64 + tx * 4) = u1;
    }
}

// ---------------------------------------------------------------------------
// Phase B: per (b,h,s) row — exact top-32 with certified threshold pruning.
// Pass 1: t = warp-min of per-lane maxima. The 32 lane maxima are 32 values
//   >= t, so the true 32nd max m32 >= t. Any candidate < t is provably not
//   in the final top-32 and is skipped (result bit-identical; ties at m32
//   have u >= t and are kept, preserving earliest-index semantics).
// Pass 2: R13 insert loop with the ballot pre-filtered by u >= t — most
//   batches short-circuit, serial accepts drop ~133 -> ~45.
// ---------------------------------------------------------------------------
__global__ __launch_bounds__(256) void select_kernel(float* __restrict__ out)
{
    __shared__ float swt[8][32];
    __shared__ int   svi[8][32];

    const int warp = threadIdx.x >> 5;
    const int lane = threadIdx.x & 31;
    const int job = blockIdx.x * 8 + warp;   // 0..65535
    const int bh = job >> 11;
    const int s  = job & 2047;
    const int b = bh >> 4, h = bh & 15;

    const unsigned* srow = g_S + (size_t)bh * NS * NS + (size_t)s * NS;

    // ---- pass 1: certified lower bound for the 32nd max
    unsigned vmax = 0u;
#pragma unroll 8
    for (int t = 0; t < 64; t++)
        vmax = max(vmax, srow[t * 32 + lane]);
    const unsigned tb = __reduce_min_sync(0xffffffffu, vmax);

    // ---- pass 2: init list from first 32 candidates (row now L1-resident)
    unsigned lu = srow[lane];
    int lidx = lane;
    unsigned umin = __reduce_min_sync(0xffffffffu, lu);
    int minlane = __ffs(__ballot_sync(0xffffffffu, lu == umin)) - 1;

    unsigned nxt[8];
#pragma unroll
    for (int j = 0; j < 8; j++) nxt[j] = srow[(1 + j) * 32 + lane];

#pragma unroll 8
    for (int t = 1; t < 64; t++) {
        const unsigned u = nxt[(t - 1) & 7];
        if (t + 8 < 64) nxt[(t - 1) & 7] = srow[(t + 8) * 32 + lane];
        const int base = t * 32;

        // pruned ballot: skip candidates provably below the final 32nd max
        unsigned bal = __ballot_sync(0xffffffffu, u >= tb && u > umin);
        while (bal) {
            const int src = __ffs(bal) - 1;
            bal &= bal - 1;
            const unsigned uv = __shfl_sync(0xffffffffu, u, src);
            if (uv > umin) {             // umin warp-uniform -> uniform branch
                if (lane == minlane) { lu = uv; lidx = base + src; }
                umin = __reduce_min_sync(0xffffffffu, lu);
                minlane = __ffs(__ballot_sync(0xffffffffu, lu == umin)) - 1;
            }
        }
    }

    // softmax over the 32 survivors (== reference masked softmax: masked
    // entries contribute exp(-1e9 - max) == 0 in fp32)
    const float lval = mono2f(lu);
    const float m = warp_max(lval);
    const float e = __expf(lval - m);
    const float w = e / warp_sum(e);

    // publish (weight, index) via smem; gather loop uses LDS broadcasts
    swt[warp][lane] = w;
    svi[warp][lane] = lidx;
    __syncwarp();

    // AV gather: lane owns output dims (2*lane, 2*lane+1)
    const float* Vb = g_Vp + (size_t)b * NS * ND + h * NDK + lane * 2;
    float2 acc = make_float2(0.f, 0.f);
#pragma unroll
    for (int t = 0; t < 32; t++) {
        const int   vi = svi[warp][t];
        const float wt = swt[warp][t];
        const float2 v = *(const float2*)(Vb + (size_t)vi * ND);
        acc.x += wt * v.x;
        acc.y += wt * v.y;
    }

    *(float2*)(out + (size_t)(b * NS + s) * ND + h * NDK + lane * 2) = acc;
}

// ---------------------------------------------------------------------------
extern "C" void kernel_launch(void* const* d_in, const int* in_sizes, int n_in,
                              void* d_out, int out_size)
{
    const float* query = (const float*)d_in[0];
    const float* key   = (const float*)d_in[1];
    const float* value = (const float*)d_in[2];
    const float* Wq    = (const float*)d_in[3];
    const float* bq    = (const float*)d_in[4];
    const float* Wk    = (const float*)d_in[5];
    const float* bk    = (const float*)d_in[6];
    const float* Wv    = (const float*)d_in[7];
    const float* bv    = (const float*)d_in[8];
    float* out = (float*)d_out;

    dim3 pgrid(ND / 128, (NB * NS) / 128, 3);
    proj_kernel<<<pgrid, 256>>>(query, Wq, bq, key, Wk, bk, value, Wv, bv);

    dim3 sgrid(NS / 128, NS / 128, NB * NH);
    score_kernel<<<sgrid, 256>>>();

    select_kernel<<<(NB * NH * NS) / 8, 256>>>(out);
}